// round 14
// baseline (speedup 1.0000x reference)
#include <cuda_runtime.h>
#include <cuda_fp16.h>
#include <stdint.h>

// ---------------------------------------------------------------------------
// Problem constants
// ---------------------------------------------------------------------------
#define CDIM 512
#define GDIM 1024
#define PDIM 128
#define MROWS (PDIM * GDIM)      // 131072
#define NUM_IDS 64
#define EPS_BN 1e-5f

// ---------------------------------------------------------------------------
// Scratch (device globals; no cudaMalloc allowed)
// ---------------------------------------------------------------------------
__device__ __half g_h1[(size_t)MROWS * CDIM];  // h1 in fp16 (128 MB)
__device__ __half g_WTh1[CDIM * CDIM];         // W1^T fp16, [N][K]
__device__ __half g_WTh2[CDIM * CDIM];         // W2^T fp16
__device__ float  g_u[MROWS * 2];              // u = t @ Wc (atomic partials)

// ---------------------------------------------------------------------------
// Helpers
// ---------------------------------------------------------------------------
__device__ __forceinline__ uint32_t smem_u32(const void* p) {
    uint32_t a;
    asm("{ .reg .u64 t; cvta.to.shared.u64 t, %1; cvt.u32.u64 %0, t; }"
        : "=r"(a) : "l"(p));
    return a;
}
__device__ __forceinline__ void cp16(uint32_t s, const void* g) {
    asm volatile("cp.async.cg.shared.global [%0], [%1], 16;" :: "r"(s), "l"(g) : "memory");
}
__device__ __forceinline__ void cp_commit() {
    asm volatile("cp.async.commit_group;" ::: "memory");
}
template <int N> __device__ __forceinline__ void cp_wait() {
    asm volatile("cp.async.wait_group %0;" :: "n"(N) : "memory");
}
__device__ __forceinline__ void ldsm4(uint32_t r[4], uint32_t addr) {
    asm volatile("ldmatrix.sync.aligned.m8n8.x4.shared.b16 {%0,%1,%2,%3}, [%4];"
                 : "=r"(r[0]), "=r"(r[1]), "=r"(r[2]), "=r"(r[3]) : "r"(addr));
}
__device__ __forceinline__ float2 lds64(uint32_t addr) {
    float2 v;
    asm volatile("ld.shared.v2.f32 {%0,%1}, [%2];"
                 : "=f"(v.x), "=f"(v.y) : "r"(addr));
    return v;
}
__device__ __forceinline__ uint32_t packh2(float2 v) {
    __half2 h = __floats2half2_rn(v.x, v.y);
    return *reinterpret_cast<uint32_t*>(&h);
}
// fp16 MMA k16: D[16,8] += A[16,16] * B[16,8], fp32 accumulate
__device__ __forceinline__ void mma_f16(float* c, const uint32_t* a, const uint32_t* b) {
    asm volatile(
        "mma.sync.aligned.m16n8k16.row.col.f32.f16.f16.f32 "
        "{%0,%1,%2,%3}, {%4,%5,%6,%7}, {%8,%9}, {%0,%1,%2,%3};"
        : "+f"(c[0]), "+f"(c[1]), "+f"(c[2]), "+f"(c[3])
        : "r"(a[0]), "r"(a[1]), "r"(a[2]), "r"(a[3]), "r"(b[0]), "r"(b[1]));
}

// ---------------------------------------------------------------------------
// Shared GEMM geometry: CTA 128x128, 128 threads (4 warps, 2x2 of 64x64)
// ---------------------------------------------------------------------------
#define BM 128
#define BN 128
#define BK 64
#define NCHUNK (CDIM / BK)       // 8

// GEMM1 (fp32 A) smem: 2-stage; A 32 KB/stage, B 16 KB/stage
#define A1TILE 32768
#define B1TILE 16384
#define A1OFF(s) ((s) * A1TILE)
#define B1OFF(s) (2 * A1TILE + (s) * B1TILE)
#define COEF1_B  (2 * A1TILE + 2 * B1TILE)     // 98304
#define SMEM1_TOTAL (COEF1_B + 1024)           // 99328 -> 2 CTAs/SM

// GEMM2 (fp16 A) smem: 3-stage ring of 16 KB tiles
#define NSTAGE 3
#define ATILE 16384
#define BOFF  (NSTAGE * ATILE)
#define COEF2_B (2 * NSTAGE * ATILE)           // 98304
#define COEF2_F (COEF2_B / 4)
#define SRED_F (COEF2_F + 512)
#define SMEM2_TOTAL ((SRED_F + 256) * 4)       // 101376 -> 2 CTAs/SM

// ---------------------------------------------------------------------------
// Prep: W^T fp16 + zero g_u (one kernel, 512 blocks x 256 threads)
// ---------------------------------------------------------------------------
__global__ void transpose_w_zero_kernel(const float* __restrict__ W1,
                                        const float* __restrict__ W2) {
    int n = blockIdx.x;
    for (int k = threadIdx.x; k < CDIM; k += blockDim.x) {
        g_WTh1[n * CDIM + k] = __float2half_rn(W1[k * CDIM + n]);
        g_WTh2[n * CDIM + k] = __float2half_rn(W2[k * CDIM + n]);
    }
    int t = blockIdx.x * blockDim.x + threadIdx.x;   // 0..131071
    g_u[t] = 0.0f;
    g_u[t + MROWS] = 0.0f;
}

// ---------------------------------------------------------------------------
// GEMM1: h1 = fp16(lrelu(bn1(d @ W1))). A read as RAW fp32, frag-converted
// post-LDS. 2-stage pipeline, software-pipelined fragments.
// A-tile swizzle: 16B-chunk q ^ (row & 7)  (conflict-free stores AND loads)
// ---------------------------------------------------------------------------
__global__ void __launch_bounds__(128, 2)
gemm1_kernel(const float* __restrict__ d,
             const float* __restrict__ bias,
             const float* __restrict__ gam,
             const float* __restrict__ bet,
             const float* __restrict__ rm,
             const float* __restrict__ rv)
{
    extern __shared__ float sm[];
    const uint32_t sbase = smem_u32(sm);

    const int tid = threadIdx.x;
    const int wid = tid >> 5;
    const int lane = tid & 31;
    const int l4 = lane & 3;
    const int lg = lane >> 2;
    const int bm = blockIdx.y * BM;
    const int bn = blockIdx.x * BN;
    const int warp_row = (wid & 1) * 64;
    const int warp_col = (wid >> 1) * 64;

    // B ldmatrix addressing (128-B fp16 rows, SW128 XOR)
    const int rlane = (lane < 16) ? lane : (lane - 16);
    const int kadd  = (lane < 16) ? 0 : 16;
    const uint32_t xmask = (uint32_t)((rlane & 7) << 4);
    const uint32_t b_row_base = sbase + B1OFF(0) + (uint32_t)(warp_col + rlane) * 128;

    // A fp32 addressing: row stride 256 B; 16B-chunk swizzle q ^ (row&7)
    const uint32_t aconst_lo = ((uint32_t)(l4 & 1)) * 8;   // (k0&3)*4 bytes
    const uint32_t xr = (uint32_t)lg;                      // row & 7 == lg

    float* sc_s = sm + COEF1_B / 4;
    float* of_s = sc_s + 128;
    {
        int col = bn + tid;
        float inv = rsqrtf(rv[col] + EPS_BN) * gam[col];
        sc_s[tid] = inv;
        of_s[tid] = (bias[col] - rm[col]) * inv + bet[col];
    }

    float acc[4][8][4];
#pragma unroll
    for (int i = 0; i < 4; i++)
#pragma unroll
        for (int j = 0; j < 8; j++)
#pragma unroll
            for (int q = 0; q < 4; q++) acc[i][j][q] = 0.0f;

    // chunk loader: A fp32 128x64 (256 B rows), B fp16 128x64 (128 B rows)
    auto load_chunk = [&](int c) {
        const int s = c & 1;
        const float* aG = d + (size_t)bm * CDIM + c * BK;
        const uint32_t aB = sbase + A1OFF(s);
#pragma unroll
        for (int i = 0; i < 16; i++) {
            int idx = tid + i * 128;
            int row = idx >> 4, q = idx & 15;
            uint32_t sw = (uint32_t)((q ^ (row & 7)) << 4);
            cp16(aB + row * 256 + sw, aG + (size_t)row * CDIM + q * 4);
        }
        const __half* bG = g_WTh1 + (size_t)bn * CDIM + c * BK;
        const uint32_t bB = sbase + B1OFF(s);
#pragma unroll
        for (int i = 0; i < 8; i++) {
            int idx = tid + i * 128;
            int row = idx >> 3, q = idx & 7;
            uint32_t sw = (uint32_t)(q * 16) ^ (uint32_t)((row & 7) << 4);
            cp16(bB + row * 128 + sw, bG + (size_t)row * CDIM + q * 8);
        }
        cp_commit();
    };

    // A fragment: 4 x LDS.64 + pack per mt (fp32 -> fp16 conversion here)
    auto lda = [&](int s, int ks, uint32_t af[4][4]) {
        const uint32_t base = sbase + A1OFF(s);
        const uint32_t chunk0 = (uint32_t)(ks * 4 + (l4 >> 1));
        const uint32_t col0 = ((chunk0 ^ xr) << 4) + aconst_lo;        // k0
        const uint32_t col1 = (((chunk0 + 2) ^ xr) << 4) + aconst_lo;  // k0+8
#pragma unroll
        for (int mt = 0; mt < 4; mt++) {
            uint32_t rb = base + (uint32_t)(warp_row + mt * 16 + lg) * 256;
            af[mt][0] = packh2(lds64(rb + col0));
            af[mt][1] = packh2(lds64(rb + 2048 + col0));
            af[mt][2] = packh2(lds64(rb + col1));
            af[mt][3] = packh2(lds64(rb + 2048 + col1));
        }
    };
    // B fragment via ldmatrix
    auto ldb = [&](int s, int kb, uint32_t bf[8][2]) {
        const uint32_t col = ((uint32_t)(kb + kadd)) ^ xmask;
        const uint32_t sb = b_row_base + (uint32_t)(s * B1TILE) + col;
#pragma unroll
        for (int ntp = 0; ntp < 4; ntp++) {
            uint32_t r[4];
            ldsm4(r, sb + ntp * (16 * 128));
            bf[2 * ntp + 0][0] = r[0];
            bf[2 * ntp + 1][0] = r[1];
            bf[2 * ntp + 0][1] = r[2];
            bf[2 * ntp + 1][1] = r[3];
        }
    };

    auto mma_all = [&](uint32_t af[4][4], uint32_t bf[8][2]) {
#pragma unroll
        for (int mt = 0; mt < 4; mt++)
#pragma unroll
            for (int nt = 0; nt < 8; nt++)
                mma_f16(acc[mt][nt], af[mt], bf[nt]);
    };

    uint32_t fA_a[4][4], fA_b[8][2];
    uint32_t fB_a[4][4], fB_b[8][2];

    // 2-stage prologue; arm chunk-0 k0 frags
    load_chunk(0);
    load_chunk(1);
    cp_wait<1>();
    __syncthreads();
    lda(0, 0, fA_a); ldb(0, 0, fA_b);

    for (int c = 0; c < NCHUNK; c++) {
        const int s = c & 1;

        lda(s, 1, fB_a); ldb(s, 32, fB_b);
        mma_all(fA_a, fA_b);                 // k 0-15
        lda(s, 2, fA_a); ldb(s, 64, fA_b);
        mma_all(fB_a, fB_b);                 // k 16-31
        lda(s, 3, fB_a); ldb(s, 96, fB_b);
        mma_all(fA_a, fA_b);                 // k 32-47
        if (c + 1 < NCHUNK) {
            cp_wait<0>();                    // chunk c+1 complete
            __syncthreads();                 // all warps done LDS on stage s
            lda(s ^ 1, 0, fA_a); ldb(s ^ 1, 0, fA_b);  // next chunk k0
            if (c + 2 < NCHUNK) load_chunk(c + 2);     // overwrite stage s
        }
        mma_all(fB_a, fB_b);                 // k 48-63 (covers LDS + load)
    }

    // epilogue: fp16(lrelu(bn1(.))) -> g_h1
#pragma unroll
    for (int mt = 0; mt < 4; mt++) {
        const int r0 = bm + warp_row + mt * 16 + lg;
#pragma unroll
        for (int nt = 0; nt < 8; nt++) {
            const int cl = warp_col + nt * 8 + l4 * 2;
            const float s0 = sc_s[cl], s1 = sc_s[cl + 1];
            const float o0 = of_s[cl], o1 = of_s[cl + 1];
            float v0, v1;
            v0 = fmaf(acc[mt][nt][0], s0, o0); v0 = v0 >= 0.f ? v0 : 0.1f * v0;
            v1 = fmaf(acc[mt][nt][1], s1, o1); v1 = v1 >= 0.f ? v1 : 0.1f * v1;
            *reinterpret_cast<__half2*>(&g_h1[(size_t)r0 * CDIM + bn + cl]) =
                __floats2half2_rn(v0, v1);
            v0 = fmaf(acc[mt][nt][2], s0, o0); v0 = v0 >= 0.f ? v0 : 0.1f * v0;
            v1 = fmaf(acc[mt][nt][3], s1, o1); v1 = v1 >= 0.f ? v1 : 0.1f * v1;
            *reinterpret_cast<__half2*>(&g_h1[(size_t)(r0 + 8) * CDIM + bn + cl]) =
                __floats2half2_rn(v0, v1);
        }
    }
}

// ---------------------------------------------------------------------------
// GEMM2: A = g_h1 fp16, 3-stage ring; epilogue folds t @ Wc into g_u
// ---------------------------------------------------------------------------
__global__ void __launch_bounds__(128, 2)
gemm2_kernel(const float* __restrict__ bias,
             const float* __restrict__ gam,
             const float* __restrict__ bet,
             const float* __restrict__ rm,
             const float* __restrict__ rv,
             const float* __restrict__ Wc)
{
    extern __shared__ float sm[];
    const uint32_t sbase = smem_u32(sm);

    const int tid = threadIdx.x;
    const int wid = tid >> 5;
    const int lane = tid & 31;
    const int l4 = lane & 3;
    const int lg = lane >> 2;
    const int bm = blockIdx.y * BM;
    const int bn = blockIdx.x * BN;
    const int warp_row = (wid & 1) * 64;
    const int warp_col = (wid >> 1) * 64;

    const int rlane = (lane < 16) ? lane : (lane - 16);
    const int kadd  = (lane < 16) ? 0 : 16;
    const uint32_t xmask = (uint32_t)((rlane & 7) << 4);
    const uint32_t a_row_base = sbase + (uint32_t)(warp_row + rlane) * 128;
    const uint32_t b_row_base = sbase + BOFF + (uint32_t)(warp_col + rlane) * 128;

    float* sc_s  = sm + COEF2_F;
    float* of_s  = sc_s + 128;
    float* wc0_s = sc_s + 256;
    float* wc1_s = sc_s + 384;
    float* sred  = sm + SRED_F;
    {
        int col = bn + tid;
        float inv = rsqrtf(rv[col] + EPS_BN) * gam[col];
        sc_s[tid] = inv;
        of_s[tid] = (bias[col] - rm[col]) * inv + bet[col];
        wc0_s[tid] = Wc[col * 2 + 0];
        wc1_s[tid] = Wc[col * 2 + 1];
        sred[tid * 2 + 0] = 0.0f;
        sred[tid * 2 + 1] = 0.0f;
    }

    float acc[4][8][4];
#pragma unroll
    for (int i = 0; i < 4; i++)
#pragma unroll
        for (int j = 0; j < 8; j++)
#pragma unroll
            for (int q = 0; q < 4; q++) acc[i][j][q] = 0.0f;

    auto load_chunk = [&](int c) {
        const int s = c % NSTAGE;
        const __half* aG = g_h1 + (size_t)bm * CDIM + c * BK;
        const uint32_t aB = sbase + s * ATILE;
#pragma unroll
        for (int i = 0; i < 8; i++) {
            int idx = tid + i * 128;
            int row = idx >> 3, q = idx & 7;
            uint32_t sw = (uint32_t)(q * 16) ^ (uint32_t)((row & 7) << 4);
            cp16(aB + row * 128 + sw, aG + (size_t)row * CDIM + q * 8);
        }
        const __half* bG = g_WTh2 + (size_t)bn * CDIM + c * BK;
        const uint32_t bB = sbase + BOFF + s * ATILE;
#pragma unroll
        for (int i = 0; i < 8; i++) {
            int idx = tid + i * 128;
            int row = idx >> 3, q = idx & 7;
            uint32_t sw = (uint32_t)(q * 16) ^ (uint32_t)((row & 7) << 4);
            cp16(bB + row * 128 + sw, bG + (size_t)row * CDIM + q * 8);
        }
        cp_commit();
    };

    auto ldfrag = [&](int s, int kb, uint32_t af[4][4], uint32_t bf[8][2]) {
        const uint32_t col = ((uint32_t)(kb + kadd)) ^ xmask;
        const uint32_t sa = a_row_base + s * ATILE + col;
        const uint32_t sb = b_row_base + s * ATILE + col;
#pragma unroll
        for (int mt = 0; mt < 4; mt++)
            ldsm4(af[mt], sa + mt * (16 * 128));
#pragma unroll
        for (int ntp = 0; ntp < 4; ntp++) {
            uint32_t r[4];
            ldsm4(r, sb + ntp * (16 * 128));
            bf[2 * ntp + 0][0] = r[0];
            bf[2 * ntp + 1][0] = r[1];
            bf[2 * ntp + 0][1] = r[2];
            bf[2 * ntp + 1][1] = r[3];
        }
    };

    auto mma_all = [&](uint32_t af[4][4], uint32_t bf[8][2]) {
#pragma unroll
        for (int mt = 0; mt < 4; mt++)
#pragma unroll
            for (int nt = 0; nt < 8; nt++)
                mma_f16(acc[mt][nt], af[mt], bf[nt]);
    };

    uint32_t fA_a[4][4], fA_b[8][2];
    uint32_t fB_a[4][4], fB_b[8][2];

    load_chunk(0);
    load_chunk(1);
    cp_wait<1>();
    __syncthreads();
    ldfrag(0, 0, fA_a, fA_b);

    for (int c = 0; c < NCHUNK; c++) {
        const int s = c % NSTAGE;

        ldfrag(s, 32, fB_a, fB_b);
        mma_all(fA_a, fA_b);
        if (c + 2 < NCHUNK) load_chunk(c + 2);
        ldfrag(s, 64, fA_a, fA_b);
        mma_all(fB_a, fB_b);
        ldfrag(s, 96, fB_a, fB_b);
        mma_all(fA_a, fA_b);
        if (c + 1 < NCHUNK) {
            if (c + 2 < NCHUNK) cp_wait<1>();
            else                cp_wait<0>();
            __syncthreads();
            ldfrag((c + 1) % NSTAGE, 0, fA_a, fA_b);
        }
        mma_all(fB_a, fB_b);
    }

    // epilogue: t = lrelu(bn2(.)); u += t . Wc
    float p[4][2][2];
#pragma unroll
    for (int mt = 0; mt < 4; mt++)
        for (int h = 0; h < 2; h++)
            for (int j = 0; j < 2; j++) p[mt][h][j] = 0.0f;
#pragma unroll
    for (int mt = 0; mt < 4; mt++) {
#pragma unroll
        for (int nt = 0; nt < 8; nt++) {
            const int cl = warp_col + nt * 8 + l4 * 2;
            const float s0 = sc_s[cl], s1 = sc_s[cl + 1];
            const float o0 = of_s[cl], o1 = of_s[cl + 1];
            const float a0 = wc0_s[cl], a1 = wc0_s[cl + 1];
            const float b0 = wc1_s[cl], b1 = wc1_s[cl + 1];
            float v00 = fmaf(acc[mt][nt][0], s0, o0); v00 = v00 >= 0.f ? v00 : 0.1f * v00;
            float v01 = fmaf(acc[mt][nt][1], s1, o1); v01 = v01 >= 0.f ? v01 : 0.1f * v01;
            float v10 = fmaf(acc[mt][nt][2], s0, o0); v10 = v10 >= 0.f ? v10 : 0.1f * v10;
            float v11 = fmaf(acc[mt][nt][3], s1, o1); v11 = v11 >= 0.f ? v11 : 0.1f * v11;
            p[mt][0][0] += v00 * a0 + v01 * a1;
            p[mt][0][1] += v00 * b0 + v01 * b1;
            p[mt][1][0] += v10 * a0 + v11 * a1;
            p[mt][1][1] += v10 * b0 + v11 * b1;
        }
    }
#pragma unroll
    for (int mt = 0; mt < 4; mt++)
#pragma unroll
        for (int h = 0; h < 2; h++)
#pragma unroll
            for (int j = 0; j < 2; j++) {
                float v = p[mt][h][j];
                v += __shfl_xor_sync(0xFFFFFFFFu, v, 1);
                v += __shfl_xor_sync(0xFFFFFFFFu, v, 2);
                p[mt][h][j] = v;
            }
    if (l4 == 0) {
#pragma unroll
        for (int mt = 0; mt < 4; mt++)
#pragma unroll
            for (int h = 0; h < 2; h++) {
                int rl = warp_row + mt * 16 + lg + h * 8;
                atomicAdd(&sred[rl * 2 + 0], p[mt][h][0]);
                atomicAdd(&sred[rl * 2 + 1], p[mt][h][1]);
            }
    }
    __syncthreads();
    atomicAdd(&g_u[(size_t)(bm + tid) * 2 + 0], sred[tid * 2 + 0]);
    atomicAdd(&g_u[(size_t)(bm + tid) * 2 + 1], sred[tid * 2 + 1]);
}

// ---------------------------------------------------------------------------
// Fused finalize: one block per p. Computes the 64 class sums + counts from
// g_u, then writes result rows (and labels). Replaces class_sums + finalize.
// ---------------------------------------------------------------------------
__global__ void finalize_kernel(const int* __restrict__ y_p,
                                const int* __restrict__ y_g,
                                const float* __restrict__ bc,
                                float* __restrict__ out, int mode)
{
    const int p = blockIdx.x;            // 0..127
    const int tid = threadIdx.x;         // 256 threads
    __shared__ float bins[NUM_IDS][2];
    __shared__ int cbin[NUM_IDS];
    __shared__ int yg_s[GDIM];

    if (tid < NUM_IDS) { bins[tid][0] = 0.0f; bins[tid][1] = 0.0f; cbin[tid] = 0; }
    __syncthreads();

    for (int g = tid; g < GDIM; g += 256) {
        int k = y_g[g];
        yg_s[g] = k;
        size_t base = ((size_t)p * GDIM + g) * 2;
        atomicAdd(&bins[k][0], g_u[base + 0]);
        atomicAdd(&bins[k][1], g_u[base + 1]);
        atomicAdd(&cbin[k], 1);
    }
    __syncthreads();

    const float b0 = bc[0], b1 = bc[1];
    const int yp = y_p[p];
    for (int h = tid; h < GDIM; h += 256) {
        int k = yg_s[h];
        float inv = 1.0f / (float)(cbin[k] + 1);
        size_t ub = ((size_t)p * GDIM + h) * 2;
        out[ub + 0] = (bins[k][0] + g_u[ub + 0]) * inv + b0;
        out[ub + 1] = (bins[k][1] + g_u[ub + 1]) * inv + b1;
        int lab = (yp == k) ? 1 : 0;     // y_p[p] == y_g[h]
        if (mode == 1) {
            out[2 * MROWS + p * GDIM + h] = (float)lab;
        } else if (mode == 2) {
            long long* lp = reinterpret_cast<long long*>(out + 2 * MROWS);
            lp[p * GDIM + h] = (long long)lab;
        }
    }
}

// ---------------------------------------------------------------------------
extern "C" void kernel_launch(void* const* d_in, const int* in_sizes, int n_in,
                              void* d_out, int out_size)
{
    const float* d   = (const float*)d_in[0];
    const int*   y_p = (const int*)d_in[1];
    const int*   y_g = (const int*)d_in[2];
    const float* W1  = (const float*)d_in[3];
    const float* b1  = (const float*)d_in[4];
    const float* g1  = (const float*)d_in[5];
    const float* be1 = (const float*)d_in[6];
    const float* rm1 = (const float*)d_in[7];
    const float* rv1 = (const float*)d_in[8];
    const float* W2  = (const float*)d_in[9];
    const float* b2  = (const float*)d_in[10];
    const float* g2  = (const float*)d_in[11];
    const float* be2 = (const float*)d_in[12];
    const float* rm2 = (const float*)d_in[13];
    const float* rv2 = (const float*)d_in[14];
    const float* Wc  = (const float*)d_in[15];
    const float* bc  = (const float*)d_in[16];
    float* out = (float*)d_out;

    int mode;
    if (out_size == 2 * MROWS) mode = 0;
    else if (out_size == 3 * MROWS) mode = 1;
    else mode = 2;

    cudaFuncSetAttribute(gemm1_kernel,
                         cudaFuncAttributeMaxDynamicSharedMemorySize, SMEM1_TOTAL);
    cudaFuncSetAttribute(gemm2_kernel,
                         cudaFuncAttributeMaxDynamicSharedMemorySize, SMEM2_TOTAL);

    transpose_w_zero_kernel<<<CDIM, 256>>>(W1, W2);

    dim3 grid(CDIM / BN, MROWS / BM);              // (4, 1024)
    gemm1_kernel<<<grid, 128, SMEM1_TOTAL>>>(d, b1, g1, be1, rm1, rv1);
    gemm2_kernel<<<grid, 128, SMEM2_TOTAL>>>(b2, g2, be2, rm2, rv2, Wc);

    finalize_kernel<<<PDIM, 256>>>(y_p, y_g, bc, out, mode);
}

// round 15
// speedup vs baseline: 1.0717x; 1.0717x over previous
#include <cuda_runtime.h>
#include <cuda_fp16.h>
#include <stdint.h>

// ---------------------------------------------------------------------------
// Problem constants
// ---------------------------------------------------------------------------
#define CDIM 512
#define GDIM 1024
#define PDIM 128
#define MROWS (PDIM * GDIM)      // 131072
#define NUM_IDS 64
#define EPS_BN 1e-5f

// ---------------------------------------------------------------------------
// Scratch (device globals; no cudaMalloc allowed)
// ---------------------------------------------------------------------------
__device__ __half g_h1[(size_t)MROWS * CDIM];  // h1 in fp16 (128 MB)
__device__ __half g_WTh1[CDIM * CDIM];         // W1^T fp16, [N][K]
__device__ __half g_WTh2[CDIM * CDIM];         // W2^T fp16
__device__ float  g_u[MROWS * 2];              // u = t @ Wc (atomic partials)

// ---------------------------------------------------------------------------
// Helpers
// ---------------------------------------------------------------------------
__device__ __forceinline__ uint32_t smem_u32(const void* p) {
    uint32_t a;
    asm("{ .reg .u64 t; cvta.to.shared.u64 t, %1; cvt.u32.u64 %0, t; }"
        : "=r"(a) : "l"(p));
    return a;
}
__device__ __forceinline__ void cp16(uint32_t s, const void* g) {
    asm volatile("cp.async.cg.shared.global [%0], [%1], 16;" :: "r"(s), "l"(g) : "memory");
}
__device__ __forceinline__ void cp_commit() {
    asm volatile("cp.async.commit_group;" ::: "memory");
}
template <int N> __device__ __forceinline__ void cp_wait() {
    asm volatile("cp.async.wait_group %0;" :: "n"(N) : "memory");
}
__device__ __forceinline__ void ldsm4(uint32_t r[4], uint32_t addr) {
    asm volatile("ldmatrix.sync.aligned.m8n8.x4.shared.b16 {%0,%1,%2,%3}, [%4];"
                 : "=r"(r[0]), "=r"(r[1]), "=r"(r[2]), "=r"(r[3]) : "r"(addr));
}
__device__ __forceinline__ float2 lds64(uint32_t addr) {
    float2 v;
    asm volatile("ld.shared.v2.f32 {%0,%1}, [%2];"
                 : "=f"(v.x), "=f"(v.y) : "r"(addr));
    return v;
}
__device__ __forceinline__ uint32_t packh2(float2 v) {
    __half2 h = __floats2half2_rn(v.x, v.y);
    return *reinterpret_cast<uint32_t*>(&h);
}
// fp16 MMA k16: D[16,8] += A[16,16] * B[16,8], fp32 accumulate
__device__ __forceinline__ void mma_f16(float* c, const uint32_t* a, const uint32_t* b) {
    asm volatile(
        "mma.sync.aligned.m16n8k16.row.col.f32.f16.f16.f32 "
        "{%0,%1,%2,%3}, {%4,%5,%6,%7}, {%8,%9}, {%0,%1,%2,%3};"
        : "+f"(c[0]), "+f"(c[1]), "+f"(c[2]), "+f"(c[3])
        : "r"(a[0]), "r"(a[1]), "r"(a[2]), "r"(a[3]), "r"(b[0]), "r"(b[1]));
}

// ---------------------------------------------------------------------------
// Shared GEMM geometry: CTA 128x128, 128 threads (4 warps, 2x2 of 64x64)
// ---------------------------------------------------------------------------
#define BM 128
#define BN 128
#define BK 64
#define NCHUNK (CDIM / BK)       // 8

// GEMM1 (fp32 A) smem: 2-stage; A 32 KB/stage, B 16 KB/stage
#define A1TILE 32768
#define B1TILE 16384
#define A1OFF(s) ((s) * A1TILE)
#define B1OFF(s) (2 * A1TILE + (s) * B1TILE)
#define COEF1_B  (2 * A1TILE + 2 * B1TILE)     // 98304
#define SMEM1_TOTAL (COEF1_B + 1024)           // 99328 -> 2 CTAs/SM

// GEMM2 (fp16 A) smem: 3-stage ring of 16 KB tiles
#define NSTAGE 3
#define ATILE 16384
#define BOFF  (NSTAGE * ATILE)
#define COEF2_B (2 * NSTAGE * ATILE)           // 98304
#define COEF2_F (COEF2_B / 4)
#define SRED_F (COEF2_F + 512)
#define SMEM2_TOTAL ((SRED_F + 256) * 4)       // 101376 -> 2 CTAs/SM

// ---------------------------------------------------------------------------
// Prep: W^T fp16 + zero g_u (one kernel, 512 blocks x 256 threads)
// ---------------------------------------------------------------------------
__global__ void transpose_w_zero_kernel(const float* __restrict__ W1,
                                        const float* __restrict__ W2) {
    int n = blockIdx.x;
    for (int k = threadIdx.x; k < CDIM; k += blockDim.x) {
        g_WTh1[n * CDIM + k] = __float2half_rn(W1[k * CDIM + n]);
        g_WTh2[n * CDIM + k] = __float2half_rn(W2[k * CDIM + n]);
    }
    int t = blockIdx.x * blockDim.x + threadIdx.x;   // 0..131071
    g_u[t] = 0.0f;
    g_u[t + MROWS] = 0.0f;
}

// ---------------------------------------------------------------------------
// GEMM1 (EXACT R13 config): h1 = fp16(lrelu(bn1(d @ W1))). A read as RAW
// fp32, frag-converted post-LDS. 2-stage pipeline, software-pipelined frags.
// A-tile swizzle: 16B-chunk q ^ ((row & 7) << 1)   [empirically best]
// ---------------------------------------------------------------------------
__global__ void __launch_bounds__(128, 2)
gemm1_kernel(const float* __restrict__ d,
             const float* __restrict__ bias,
             const float* __restrict__ gam,
             const float* __restrict__ bet,
             const float* __restrict__ rm,
             const float* __restrict__ rv)
{
    extern __shared__ float sm[];
    const uint32_t sbase = smem_u32(sm);

    const int tid = threadIdx.x;
    const int wid = tid >> 5;
    const int lane = tid & 31;
    const int l4 = lane & 3;
    const int lg = lane >> 2;
    const int bm = blockIdx.y * BM;
    const int bn = blockIdx.x * BN;
    const int warp_row = (wid & 1) * 64;
    const int warp_col = (wid >> 1) * 64;

    // B ldmatrix addressing (128-B fp16 rows, SW128 XOR)
    const int rlane = (lane < 16) ? lane : (lane - 16);
    const int kadd  = (lane < 16) ? 0 : 16;
    const uint32_t xmask = (uint32_t)((rlane & 7) << 4);
    const uint32_t b_row_base = sbase + B1OFF(0) + (uint32_t)(warp_col + rlane) * 128;

    // A fp32 addressing: row stride 256 B; 16B-chunk swizzle q ^ ((row&7)<<1)
    const uint32_t aconst_lo = ((uint32_t)(l4 & 1)) * 8;   // (k0&3)*4 bytes
    const uint32_t xr2 = (uint32_t)(lg << 1);              // (row&7)<<1

    float* sc_s = sm + COEF1_B / 4;
    float* of_s = sc_s + 128;
    {
        int col = bn + tid;
        float inv = rsqrtf(rv[col] + EPS_BN) * gam[col];
        sc_s[tid] = inv;
        of_s[tid] = (bias[col] - rm[col]) * inv + bet[col];
    }

    float acc[4][8][4];
#pragma unroll
    for (int i = 0; i < 4; i++)
#pragma unroll
        for (int j = 0; j < 8; j++)
#pragma unroll
            for (int q = 0; q < 4; q++) acc[i][j][q] = 0.0f;

    // chunk loader: A fp32 128x64 (256 B rows), B fp16 128x64 (128 B rows)
    auto load_chunk = [&](int c) {
        const int s = c & 1;
        const float* aG = d + (size_t)bm * CDIM + c * BK;
        const uint32_t aB = sbase + A1OFF(s);
#pragma unroll
        for (int i = 0; i < 16; i++) {
            int idx = tid + i * 128;
            int row = idx >> 4, q = idx & 15;
            uint32_t sw = (uint32_t)((q ^ ((row & 7) << 1)) << 4);
            cp16(aB + row * 256 + sw, aG + (size_t)row * CDIM + q * 4);
        }
        const __half* bG = g_WTh1 + (size_t)bn * CDIM + c * BK;
        const uint32_t bB = sbase + B1OFF(s);
#pragma unroll
        for (int i = 0; i < 8; i++) {
            int idx = tid + i * 128;
            int row = idx >> 3, q = idx & 7;
            uint32_t sw = (uint32_t)(q * 16) ^ (uint32_t)((row & 7) << 4);
            cp16(bB + row * 128 + sw, bG + (size_t)row * CDIM + q * 8);
        }
        cp_commit();
    };

    // A fragment: 4 x LDS.64 + pack per mt (fp32 -> fp16 conversion here)
    auto lda = [&](int s, int ks, uint32_t af[4][4]) {
        const uint32_t base = sbase + A1OFF(s);
        const uint32_t chunk0 = (uint32_t)(ks * 4 + (l4 >> 1));
        const uint32_t col0 = ((chunk0 ^ xr2) << 4) + aconst_lo;        // k0
        const uint32_t col1 = (((chunk0 + 2) ^ xr2) << 4) + aconst_lo;  // k0+8
#pragma unroll
        for (int mt = 0; mt < 4; mt++) {
            uint32_t rb = base + (uint32_t)(warp_row + mt * 16 + lg) * 256;
            af[mt][0] = packh2(lds64(rb + col0));
            af[mt][1] = packh2(lds64(rb + 2048 + col0));
            af[mt][2] = packh2(lds64(rb + col1));
            af[mt][3] = packh2(lds64(rb + 2048 + col1));
        }
    };
    // B fragment via ldmatrix
    auto ldb = [&](int s, int kb, uint32_t bf[8][2]) {
        const uint32_t col = ((uint32_t)(kb + kadd)) ^ xmask;
        const uint32_t sb = b_row_base + (uint32_t)(s * B1TILE) + col;
#pragma unroll
        for (int ntp = 0; ntp < 4; ntp++) {
            uint32_t r[4];
            ldsm4(r, sb + ntp * (16 * 128));
            bf[2 * ntp + 0][0] = r[0];
            bf[2 * ntp + 1][0] = r[1];
            bf[2 * ntp + 0][1] = r[2];
            bf[2 * ntp + 1][1] = r[3];
        }
    };

    auto mma_all = [&](uint32_t af[4][4], uint32_t bf[8][2]) {
#pragma unroll
        for (int mt = 0; mt < 4; mt++)
#pragma unroll
            for (int nt = 0; nt < 8; nt++)
                mma_f16(acc[mt][nt], af[mt], bf[nt]);
    };

    uint32_t fA_a[4][4], fA_b[8][2];
    uint32_t fB_a[4][4], fB_b[8][2];

    // 2-stage prologue; arm chunk-0 k0 frags
    load_chunk(0);
    load_chunk(1);
    cp_wait<1>();
    __syncthreads();
    lda(0, 0, fA_a); ldb(0, 0, fA_b);

    for (int c = 0; c < NCHUNK; c++) {
        const int s = c & 1;

        lda(s, 1, fB_a); ldb(s, 32, fB_b);
        mma_all(fA_a, fA_b);                 // k 0-15
        lda(s, 2, fA_a); ldb(s, 64, fA_b);
        mma_all(fB_a, fB_b);                 // k 16-31
        lda(s, 3, fB_a); ldb(s, 96, fB_b);
        mma_all(fA_a, fA_b);                 // k 32-47
        if (c + 1 < NCHUNK) {
            cp_wait<0>();                    // chunk c+1 complete
            __syncthreads();                 // all warps done LDS on stage s
            lda(s ^ 1, 0, fA_a); ldb(s ^ 1, 0, fA_b);  // next chunk k0
            if (c + 2 < NCHUNK) load_chunk(c + 2);     // overwrite stage s
        }
        mma_all(fB_a, fB_b);                 // k 48-63 (covers LDS + load)
    }

    // epilogue: fp16(lrelu(bn1(.))) -> g_h1
#pragma unroll
    for (int mt = 0; mt < 4; mt++) {
        const int r0 = bm + warp_row + mt * 16 + lg;
#pragma unroll
        for (int nt = 0; nt < 8; nt++) {
            const int cl = warp_col + nt * 8 + l4 * 2;
            const float s0 = sc_s[cl], s1 = sc_s[cl + 1];
            const float o0 = of_s[cl], o1 = of_s[cl + 1];
            float v0, v1;
            v0 = fmaf(acc[mt][nt][0], s0, o0); v0 = v0 >= 0.f ? v0 : 0.1f * v0;
            v1 = fmaf(acc[mt][nt][1], s1, o1); v1 = v1 >= 0.f ? v1 : 0.1f * v1;
            *reinterpret_cast<__half2*>(&g_h1[(size_t)r0 * CDIM + bn + cl]) =
                __floats2half2_rn(v0, v1);
            v0 = fmaf(acc[mt][nt][2], s0, o0); v0 = v0 >= 0.f ? v0 : 0.1f * v0;
            v1 = fmaf(acc[mt][nt][3], s1, o1); v1 = v1 >= 0.f ? v1 : 0.1f * v1;
            *reinterpret_cast<__half2*>(&g_h1[(size_t)(r0 + 8) * CDIM + bn + cl]) =
                __floats2half2_rn(v0, v1);
        }
    }
}

// ---------------------------------------------------------------------------
// GEMM2: A = g_h1 fp16, 3-stage ring; epilogue folds t @ Wc into g_u
// ---------------------------------------------------------------------------
__global__ void __launch_bounds__(128, 2)
gemm2_kernel(const float* __restrict__ bias,
             const float* __restrict__ gam,
             const float* __restrict__ bet,
             const float* __restrict__ rm,
             const float* __restrict__ rv,
             const float* __restrict__ Wc)
{
    extern __shared__ float sm[];
    const uint32_t sbase = smem_u32(sm);

    const int tid = threadIdx.x;
    const int wid = tid >> 5;
    const int lane = tid & 31;
    const int l4 = lane & 3;
    const int lg = lane >> 2;
    const int bm = blockIdx.y * BM;
    const int bn = blockIdx.x * BN;
    const int warp_row = (wid & 1) * 64;
    const int warp_col = (wid >> 1) * 64;

    const int rlane = (lane < 16) ? lane : (lane - 16);
    const int kadd  = (lane < 16) ? 0 : 16;
    const uint32_t xmask = (uint32_t)((rlane & 7) << 4);
    const uint32_t a_row_base = sbase + (uint32_t)(warp_row + rlane) * 128;
    const uint32_t b_row_base = sbase + BOFF + (uint32_t)(warp_col + rlane) * 128;

    float* sc_s  = sm + COEF2_F;
    float* of_s  = sc_s + 128;
    float* wc0_s = sc_s + 256;
    float* wc1_s = sc_s + 384;
    float* sred  = sm + SRED_F;
    {
        int col = bn + tid;
        float inv = rsqrtf(rv[col] + EPS_BN) * gam[col];
        sc_s[tid] = inv;
        of_s[tid] = (bias[col] - rm[col]) * inv + bet[col];
        wc0_s[tid] = Wc[col * 2 + 0];
        wc1_s[tid] = Wc[col * 2 + 1];
        sred[tid * 2 + 0] = 0.0f;
        sred[tid * 2 + 1] = 0.0f;
    }

    float acc[4][8][4];
#pragma unroll
    for (int i = 0; i < 4; i++)
#pragma unroll
        for (int j = 0; j < 8; j++)
#pragma unroll
            for (int q = 0; q < 4; q++) acc[i][j][q] = 0.0f;

    auto load_chunk = [&](int c) {
        const int s = c % NSTAGE;
        const __half* aG = g_h1 + (size_t)bm * CDIM + c * BK;
        const uint32_t aB = sbase + s * ATILE;
#pragma unroll
        for (int i = 0; i < 8; i++) {
            int idx = tid + i * 128;
            int row = idx >> 3, q = idx & 7;
            uint32_t sw = (uint32_t)(q * 16) ^ (uint32_t)((row & 7) << 4);
            cp16(aB + row * 128 + sw, aG + (size_t)row * CDIM + q * 8);
        }
        const __half* bG = g_WTh2 + (size_t)bn * CDIM + c * BK;
        const uint32_t bB = sbase + BOFF + s * ATILE;
#pragma unroll
        for (int i = 0; i < 8; i++) {
            int idx = tid + i * 128;
            int row = idx >> 3, q = idx & 7;
            uint32_t sw = (uint32_t)(q * 16) ^ (uint32_t)((row & 7) << 4);
            cp16(bB + row * 128 + sw, bG + (size_t)row * CDIM + q * 8);
        }
        cp_commit();
    };

    auto ldfrag = [&](int s, int kb, uint32_t af[4][4], uint32_t bf[8][2]) {
        const uint32_t col = ((uint32_t)(kb + kadd)) ^ xmask;
        const uint32_t sa = a_row_base + s * ATILE + col;
        const uint32_t sb = b_row_base + s * ATILE + col;
#pragma unroll
        for (int mt = 0; mt < 4; mt++)
            ldsm4(af[mt], sa + mt * (16 * 128));
#pragma unroll
        for (int ntp = 0; ntp < 4; ntp++) {
            uint32_t r[4];
            ldsm4(r, sb + ntp * (16 * 128));
            bf[2 * ntp + 0][0] = r[0];
            bf[2 * ntp + 1][0] = r[1];
            bf[2 * ntp + 0][1] = r[2];
            bf[2 * ntp + 1][1] = r[3];
        }
    };

    auto mma_all = [&](uint32_t af[4][4], uint32_t bf[8][2]) {
#pragma unroll
        for (int mt = 0; mt < 4; mt++)
#pragma unroll
            for (int nt = 0; nt < 8; nt++)
                mma_f16(acc[mt][nt], af[mt], bf[nt]);
    };

    uint32_t fA_a[4][4], fA_b[8][2];
    uint32_t fB_a[4][4], fB_b[8][2];

    load_chunk(0);
    load_chunk(1);
    cp_wait<1>();
    __syncthreads();
    ldfrag(0, 0, fA_a, fA_b);

    for (int c = 0; c < NCHUNK; c++) {
        const int s = c % NSTAGE;

        ldfrag(s, 32, fB_a, fB_b);
        mma_all(fA_a, fA_b);
        if (c + 2 < NCHUNK) load_chunk(c + 2);
        ldfrag(s, 64, fA_a, fA_b);
        mma_all(fB_a, fB_b);
        ldfrag(s, 96, fB_a, fB_b);
        mma_all(fA_a, fA_b);
        if (c + 1 < NCHUNK) {
            if (c + 2 < NCHUNK) cp_wait<1>();
            else                cp_wait<0>();
            __syncthreads();
            ldfrag((c + 1) % NSTAGE, 0, fA_a, fA_b);
        }
        mma_all(fB_a, fB_b);
    }

    // epilogue: t = lrelu(bn2(.)); u += t . Wc
    float p[4][2][2];
#pragma unroll
    for (int mt = 0; mt < 4; mt++)
        for (int h = 0; h < 2; h++)
            for (int j = 0; j < 2; j++) p[mt][h][j] = 0.0f;
#pragma unroll
    for (int mt = 0; mt < 4; mt++) {
#pragma unroll
        for (int nt = 0; nt < 8; nt++) {
            const int cl = warp_col + nt * 8 + l4 * 2;
            const float s0 = sc_s[cl], s1 = sc_s[cl + 1];
            const float o0 = of_s[cl], o1 = of_s[cl + 1];
            const float a0 = wc0_s[cl], a1 = wc0_s[cl + 1];
            const float b0 = wc1_s[cl], b1 = wc1_s[cl + 1];
            float v00 = fmaf(acc[mt][nt][0], s0, o0); v00 = v00 >= 0.f ? v00 : 0.1f * v00;
            float v01 = fmaf(acc[mt][nt][1], s1, o1); v01 = v01 >= 0.f ? v01 : 0.1f * v01;
            float v10 = fmaf(acc[mt][nt][2], s0, o0); v10 = v10 >= 0.f ? v10 : 0.1f * v10;
            float v11 = fmaf(acc[mt][nt][3], s1, o1); v11 = v11 >= 0.f ? v11 : 0.1f * v11;
            p[mt][0][0] += v00 * a0 + v01 * a1;
            p[mt][0][1] += v00 * b0 + v01 * b1;
            p[mt][1][0] += v10 * a0 + v11 * a1;
            p[mt][1][1] += v10 * b0 + v11 * b1;
        }
    }
#pragma unroll
    for (int mt = 0; mt < 4; mt++)
#pragma unroll
        for (int h = 0; h < 2; h++)
#pragma unroll
            for (int j = 0; j < 2; j++) {
                float v = p[mt][h][j];
                v += __shfl_xor_sync(0xFFFFFFFFu, v, 1);
                v += __shfl_xor_sync(0xFFFFFFFFu, v, 2);
                p[mt][h][j] = v;
            }
    if (l4 == 0) {
#pragma unroll
        for (int mt = 0; mt < 4; mt++)
#pragma unroll
            for (int h = 0; h < 2; h++) {
                int rl = warp_row + mt * 16 + lg + h * 8;
                atomicAdd(&sred[rl * 2 + 0], p[mt][h][0]);
                atomicAdd(&sred[rl * 2 + 1], p[mt][h][1]);
            }
    }
    __syncthreads();
    atomicAdd(&g_u[(size_t)(bm + tid) * 2 + 0], sred[tid * 2 + 0]);
    atomicAdd(&g_u[(size_t)(bm + tid) * 2 + 1], sred[tid * 2 + 1]);
}

// ---------------------------------------------------------------------------
// Fused finalize: one block per p. Computes the 64 class sums + counts from
// g_u, then writes result rows (and labels). Replaces class_sums + finalize.
// ---------------------------------------------------------------------------
__global__ void finalize_kernel(const int* __restrict__ y_p,
                                const int* __restrict__ y_g,
                                const float* __restrict__ bc,
                                float* __restrict__ out, int mode)
{
    const int p = blockIdx.x;            // 0..127
    const int tid = threadIdx.x;         // 256 threads
    __shared__ float bins[NUM_IDS][2];
    __shared__ int cbin[NUM_IDS];
    __shared__ int yg_s[GDIM];

    if (tid < NUM_IDS) { bins[tid][0] = 0.0f; bins[tid][1] = 0.0f; cbin[tid] = 0; }
    __syncthreads();

    for (int g = tid; g < GDIM; g += 256) {
        int k = y_g[g];
        yg_s[g] = k;
        size_t base = ((size_t)p * GDIM + g) * 2;
        atomicAdd(&bins[k][0], g_u[base + 0]);
        atomicAdd(&bins[k][1], g_u[base + 1]);
        atomicAdd(&cbin[k], 1);
    }
    __syncthreads();

    const float b0 = bc[0], b1 = bc[1];
    const int yp = y_p[p];
    for (int h = tid; h < GDIM; h += 256) {
        int k = yg_s[h];
        float inv = 1.0f / (float)(cbin[k] + 1);
        size_t ub = ((size_t)p * GDIM + h) * 2;
        out[ub + 0] = (bins[k][0] + g_u[ub + 0]) * inv + b0;
        out[ub + 1] = (bins[k][1] + g_u[ub + 1]) * inv + b1;
        int lab = (yp == k) ? 1 : 0;     // y_p[p] == y_g[h]
        if (mode == 1) {
            out[2 * MROWS + p * GDIM + h] = (float)lab;
        } else if (mode == 2) {
            long long* lp = reinterpret_cast<long long*>(out + 2 * MROWS);
            lp[p * GDIM + h] = (long long)lab;
        }
    }
}

// ---------------------------------------------------------------------------
extern "C" void kernel_launch(void* const* d_in, const int* in_sizes, int n_in,
                              void* d_out, int out_size)
{
    const float* d   = (const float*)d_in[0];
    const int*   y_p = (const int*)d_in[1];
    const int*   y_g = (const int*)d_in[2];
    const float* W1  = (const float*)d_in[3];
    const float* b1  = (const float*)d_in[4];
    const float* g1  = (const float*)d_in[5];
    const float* be1 = (const float*)d_in[6];
    const float* rm1 = (const float*)d_in[7];
    const float* rv1 = (const float*)d_in[8];
    const float* W2  = (const float*)d_in[9];
    const float* b2  = (const float*)d_in[10];
    const float* g2  = (const float*)d_in[11];
    const float* be2 = (const float*)d_in[12];
    const float* rm2 = (const float*)d_in[13];
    const float* rv2 = (const float*)d_in[14];
    const float* Wc  = (const float*)d_in[15];
    const float* bc  = (const float*)d_in[16];
    float* out = (float*)d_out;

    int mode;
    if (out_size == 2 * MROWS) mode = 0;
    else if (out_size == 3 * MROWS) mode = 1;
    else mode = 2;

    cudaFuncSetAttribute(gemm1_kernel,
                         cudaFuncAttributeMaxDynamicSharedMemorySize, SMEM1_TOTAL);
    cudaFuncSetAttribute(gemm2_kernel,
                         cudaFuncAttributeMaxDynamicSharedMemorySize, SMEM2_TOTAL);

    transpose_w_zero_kernel<<<CDIM, 256>>>(W1, W2);

    dim3 grid(CDIM / BN, MROWS / BM);              // (4, 1024)
    gemm1_kernel<<<grid, 128, SMEM1_TOTAL>>>(d, b1, g1, be1, rm1, rv1);
    gemm2_kernel<<<grid, 128, SMEM2_TOTAL>>>(b2, g2, be2, rm2, rv2, Wc);

    finalize_kernel<<<PDIM, 256>>>(y_p, y_g, bc, out, mode);
}